// round 15
// baseline (speedup 1.0000x reference)
#include <cuda_runtime.h>
#include <cuda_bf16.h>
#include <math.h>
#include <stdint.h>
#include <string.h>

#define B_   2
#define S_   2048
#define HID_ 4096
#define H_   32
#define KH_  8
#define D_   128
#define WIN_ 1024
#define M_TOK (B_*S_)   // 4096 tokens
#define NQKV (H_*D_ + 2*KH_*D_)   // 6144

// ---------------------------------------------------------------------------
// Scratch (__device__ globals; no allocation allowed)
// ---------------------------------------------------------------------------
__device__ float g_qkv[M_TOK * NQKV];            // fused QKV output (fp32)

__device__ __nv_bfloat16 g_Ahi[M_TOK * HID_];    // activation splits
__device__ __nv_bfloat16 g_Alo[M_TOK * HID_];
__device__ __nv_bfloat16 g_Wqkvhi[NQKV * HID_];  // fused QKV weights [N][K]
__device__ __nv_bfloat16 g_Wqkvlo[NQKV * HID_];
__device__ __nv_bfloat16 g_Wohi[HID_ * (H_*D_)];
__device__ __nv_bfloat16 g_Wolo[HID_ * (H_*D_)];

// attention operands, bf16 hi/lo
__device__ __nv_bfloat16 g_qh[M_TOK * H_  * D_];
__device__ __nv_bfloat16 g_ql[M_TOK * H_  * D_];
__device__ __nv_bfloat16 g_kh[M_TOK * KH_ * D_];
__device__ __nv_bfloat16 g_kl[M_TOK * KH_ * D_];
__device__ __nv_bfloat16 g_vh[M_TOK * KH_ * D_];
__device__ __nv_bfloat16 g_vl[M_TOK * KH_ * D_];

// ---------------------------------------------------------------------------
// PTX helpers (family-target safe)
// ---------------------------------------------------------------------------
__device__ __forceinline__ uint32_t smem_u32(const void* p) {
    uint32_t a;
    asm("{ .reg .u64 t; cvta.to.shared.u64 t, %1; cvt.u32.u64 %0, t; }"
        : "=r"(a) : "l"(p));
    return a;
}
#define CP_ASYNC16(saddr, gaddr) \
    asm volatile("cp.async.cg.shared.global [%0], [%1], 16;" \
                 :: "r"(saddr), "l"(gaddr))
#define CP_COMMIT() asm volatile("cp.async.commit_group;" ::: "memory")
template <int N>
__device__ __forceinline__ void cp_wait() {
    asm volatile("cp.async.wait_group %0;" :: "n"(N) : "memory");
}
#define LDSM4(r, a) \
    asm volatile("ldmatrix.sync.aligned.m8n8.x4.shared.b16 {%0,%1,%2,%3}, [%4];" \
                 : "=r"((r)[0]), "=r"((r)[1]), "=r"((r)[2]), "=r"((r)[3]) : "r"(a))
#define LDSM4T(r, a) \
    asm volatile("ldmatrix.sync.aligned.m8n8.x4.trans.shared.b16 {%0,%1,%2,%3}, [%4];" \
                 : "=r"((r)[0]), "=r"((r)[1]), "=r"((r)[2]), "=r"((r)[3]) : "r"(a))
#define MMA16816(c, a, b0v, b1v) \
    asm volatile("mma.sync.aligned.m16n8k16.row.col.f32.bf16.bf16.f32 " \
                 "{%0,%1,%2,%3}, {%4,%5,%6,%7}, {%8,%9}, {%0,%1,%2,%3};" \
                 : "+f"((c)[0]), "+f"((c)[1]), "+f"((c)[2]), "+f"((c)[3]) \
                 : "r"((a)[0]), "r"((a)[1]), "r"((a)[2]), "r"((a)[3]), \
                   "r"(b0v), "r"(b1v))

__device__ __forceinline__ float ex2(float x) {
    float y;
    asm("ex2.approx.ftz.f32 %0, %1;" : "=f"(y) : "f"(x));
    return y;
}
__device__ __forceinline__ uint32_t pack_bf2(float x, float y) {
    __nv_bfloat162 h = __floats2bfloat162_rn(x, y);
    uint32_t u;
    memcpy(&u, &h, 4);
    return u;
}

// ---------------------------------------------------------------------------
// Split fp32 -> (hi, lo) bf16, same layout. n must be /4.
// ---------------------------------------------------------------------------
__global__ void split_kernel(const float* __restrict__ in,
                             __nv_bfloat16* __restrict__ hi,
                             __nv_bfloat16* __restrict__ lo, int n4)
{
    int i = blockIdx.x * blockDim.x + threadIdx.x;
    if (i >= n4) return;
    float4 v = reinterpret_cast<const float4*>(in)[i];
    __nv_bfloat16 h0 = __float2bfloat16_rn(v.x);
    __nv_bfloat16 h1 = __float2bfloat16_rn(v.y);
    __nv_bfloat16 h2 = __float2bfloat16_rn(v.z);
    __nv_bfloat16 h3 = __float2bfloat16_rn(v.w);
    __nv_bfloat162 hp0; hp0.x = h0; hp0.y = h1;
    __nv_bfloat162 hp1; hp1.x = h2; hp1.y = h3;
    reinterpret_cast<__nv_bfloat162*>(hi)[i * 2]     = hp0;
    reinterpret_cast<__nv_bfloat162*>(hi)[i * 2 + 1] = hp1;
    __nv_bfloat162 lp0, lp1;
    lp0.x = __float2bfloat16_rn(v.x - __bfloat162float(h0));
    lp0.y = __float2bfloat16_rn(v.y - __bfloat162float(h1));
    lp1.x = __float2bfloat16_rn(v.z - __bfloat162float(h2));
    lp1.y = __float2bfloat16_rn(v.w - __bfloat162float(h3));
    reinterpret_cast<__nv_bfloat162*>(lo)[i * 2]     = lp0;
    reinterpret_cast<__nv_bfloat162*>(lo)[i * 2 + 1] = lp1;
}

// ---------------------------------------------------------------------------
// Split + transpose: w[K,N] fp32 -> hi/lo[N,K] bf16.
// ---------------------------------------------------------------------------
__global__ void split_T_kernel(const float* __restrict__ w,
                               __nv_bfloat16* __restrict__ hi,
                               __nv_bfloat16* __restrict__ lo, int K, int N)
{
    __shared__ float t[32][33];
    int k0 = blockIdx.y * 32, n0 = blockIdx.x * 32;
    int tx = threadIdx.x, ty = threadIdx.y;
    #pragma unroll
    for (int r = 0; r < 4; r++)
        t[ty + 8 * r][tx] = w[(size_t)(k0 + ty + 8 * r) * N + n0 + tx];
    __syncthreads();
    #pragma unroll
    for (int r = 0; r < 4; r++) {
        int n = ty + 8 * r;
        float x = t[tx][n];
        __nv_bfloat16 h = __float2bfloat16_rn(x);
        float rem = x - __bfloat162float(h);
        size_t o = (size_t)(n0 + n) * K + k0 + tx;
        hi[o] = h;
        lo[o] = __float2bfloat16_rn(rem);
    }
}

// ---------------------------------------------------------------------------
// Split-bf16 GEMM via mma.sync (HMMA): C = Ahi*Whi + Ahi*Wlo + Alo*Whi
// from 4 staged tiles per BK=32 chunk. 128x128 tile, 3-stage cp.async ring,
// XOR-swizzled 64B rows, one barrier/iter, 96KB smem, 2 CTAs/SM.
// bl LDSM hoisted above term-1 MMAs (R14 — measured win).
// ---------------------------------------------------------------------------
#define G_TILE     8192
#define G_STAGE    (4 * G_TILE)
#define G_NSTAGE   3
#define GEMM_SMEM  (G_NSTAGE * G_STAGE)   // 98304

__global__ __launch_bounds__(256, 2)
void gemm_split_kernel(const __nv_bfloat16* __restrict__ Ahi,
                       const __nv_bfloat16* __restrict__ Alo,
                       const __nv_bfloat16* __restrict__ Whi,
                       const __nv_bfloat16* __restrict__ Wlo,
                       float* __restrict__ C, int M, int N, int K)
{
    extern __shared__ char smc[];
    const uint32_t sbase = smem_u32(smc);

    const int tid  = threadIdx.x;
    const int wid  = tid >> 5;
    const int lane = tid & 31;
    const int wm   = wid >> 2;
    const int wn   = wid & 3;
    const int m0   = blockIdx.y * 128;
    const int n0   = blockIdx.x * 128;

    const int nk = K >> 5;

    float acc[4][4][4];
    #pragma unroll
    for (int i = 0; i < 4; i++)
        #pragma unroll
        for (int j = 0; j < 4; j++)
            #pragma unroll
            for (int q = 0; q < 4; q++) acc[i][j][q] = 0.0f;

    auto load_stage = [&](int kt, int buf) {
        int k0 = kt << 5;
        uint32_t sb0 = sbase + buf * G_STAGE;
        #pragma unroll
        for (int l = 0; l < 8; l++) {
            int c    = tid + l * 256;
            int tile = c >> 9;
            int rem  = c & 511;
            int row  = rem >> 2, ch = rem & 3;
            int chs  = ch ^ ((row >> 1) & 3);
            const __nv_bfloat16* src;
            int rbase;
            if (tile == 0)      { src = Ahi; rbase = m0; }
            else if (tile == 1) { src = Alo; rbase = m0; }
            else if (tile == 2) { src = Whi; rbase = n0; }
            else                { src = Wlo; rbase = n0; }
            CP_ASYNC16(sb0 + tile * G_TILE + row * 64 + chs * 16,
                       src + (size_t)(rbase + row) * K + k0 + ch * 8);
        }
        CP_COMMIT();
    };

    load_stage(0, 0);
    if (nk > 1) load_stage(1, 1);

    const int      xf       = (lane >> 1) & 3;
    const uint32_t a_rowoff = (uint32_t)(wm * 64 + (lane & 15)) * 64;
    const uint32_t b_rowoff = (uint32_t)(wn * 32 + (lane & 7)
                                         + ((lane >> 4) & 1) * 8) * 64;
    const int ca_base = lane >> 4;
    const int cb_base = (lane >> 3) & 1;

    for (int kt = 0; kt < nk; kt++) {
        if (kt + 1 < nk) cp_wait<1>(); else cp_wait<0>();
        __syncthreads();
        if (kt + 2 < nk) load_stage(kt + 2, (kt + 2) % G_NSTAGE);

        const uint32_t stg = sbase + (kt % G_NSTAGE) * G_STAGE;
        const uint32_t aAh = stg + a_rowoff;
        const uint32_t aAl = aAh + G_TILE;
        const uint32_t aWh = stg + 2 * G_TILE + b_rowoff;
        const uint32_t aWl = aWh + G_TILE;

        #pragma unroll
        for (int ks = 0; ks < 2; ks++) {
            const uint32_t ao = (uint32_t)(((ks * 2 + ca_base) ^ xf) * 16);
            const uint32_t bo = (uint32_t)(((ks * 2 + cb_base) ^ xf) * 16);
            uint32_t ah[4][4];
            #pragma unroll
            for (int mt = 0; mt < 4; mt++)
                LDSM4(ah[mt], aAh + mt * 1024 + ao);
            uint32_t bh[2][4];
            #pragma unroll
            for (int nt2 = 0; nt2 < 2; nt2++)
                LDSM4(bh[nt2], aWh + nt2 * 1024 + bo);
            uint32_t bl[2][4];
            #pragma unroll
            for (int nt2 = 0; nt2 < 2; nt2++)
                LDSM4(bl[nt2], aWl + nt2 * 1024 + bo);
            // term 1: Ahi * Whi
            #pragma unroll
            for (int mt = 0; mt < 4; mt++)
                #pragma unroll
                for (int nt = 0; nt < 4; nt++)
                    MMA16816(acc[mt][nt], ah[mt],
                             bh[nt >> 1][(nt & 1) * 2],
                             bh[nt >> 1][(nt & 1) * 2 + 1]);
            // term 2: Ahi * Wlo
            #pragma unroll
            for (int mt = 0; mt < 4; mt++)
                #pragma unroll
                for (int nt = 0; nt < 4; nt++)
                    MMA16816(acc[mt][nt], ah[mt],
                             bl[nt >> 1][(nt & 1) * 2],
                             bl[nt >> 1][(nt & 1) * 2 + 1]);
            // term 3: Alo * Whi
            {
                uint32_t al[4][4];
                #pragma unroll
                for (int mt = 0; mt < 4; mt++)
                    LDSM4(al[mt], aAl + mt * 1024 + ao);
                #pragma unroll
                for (int mt = 0; mt < 4; mt++)
                    #pragma unroll
                    for (int nt = 0; nt < 4; nt++)
                        MMA16816(acc[mt][nt], al[mt],
                                 bh[nt >> 1][(nt & 1) * 2],
                                 bh[nt >> 1][(nt & 1) * 2 + 1]);
            }
        }
    }

    #pragma unroll
    for (int mt = 0; mt < 4; mt++) {
        int row0 = m0 + wm * 64 + mt * 16 + (lane >> 2);
        #pragma unroll
        for (int nt = 0; nt < 4; nt++) {
            int col = n0 + wn * 32 + nt * 8 + 2 * (lane & 3);
            float2 v0 = make_float2(acc[mt][nt][0], acc[mt][nt][1]);
            float2 v1 = make_float2(acc[mt][nt][2], acc[mt][nt][3]);
            *reinterpret_cast<float2*>(&C[(size_t)row0 * N + col])       = v0;
            *reinterpret_cast<float2*>(&C[(size_t)(row0 + 8) * N + col]) = v1;
        }
    }
}

// ---------------------------------------------------------------------------
// RoPE + split from fused g_qkv.
// ---------------------------------------------------------------------------
__device__ __forceinline__ void split_store(__nv_bfloat16* hi, __nv_bfloat16* lo,
                                            size_t o, float x) {
    __nv_bfloat16 h = __float2bfloat16_rn(x);
    hi[o] = h;
    lo[o] = __float2bfloat16_rn(x - __bfloat162float(h));
}

__global__ void rope_split_kernel(const int* __restrict__ pos)
{
    const float QS = 0.08838834764831845f * 1.4426950408889634f;
    int idx = blockIdx.x * blockDim.x + threadIdx.x;
    const int nq = M_TOK * H_  * 64;
    const int nk = M_TOK * KH_ * 64;
    const int nv = M_TOK * KH_ * 64;

    if (idx < nq) {
        int dp = idx & 63; int r = idx >> 6;
        int hh = r & 31;   int t = r >> 5;
        const float* base = g_qkv + (size_t)t * NQKV + hh * D_;
        float p   = (float)pos[t];
        float ang = p * exp2f((float)dp * (-19.931568569324174f / 64.0f));
        float sn, cs; sincosf(ang, &sn, &cs);
        float x1 = base[dp], x2 = base[dp + 64];
        float y1 = (x1 * cs - x2 * sn) * QS;
        float y2 = (x2 * cs + x1 * sn) * QS;
        size_t o = ((size_t)t * H_ + hh) * D_;
        split_store(g_qh, g_ql, o + dp,      y1);
        split_store(g_qh, g_ql, o + dp + 64, y2);
        return;
    }
    idx -= nq;
    if (idx < nk) {
        int dp = idx & 63; int r = idx >> 6;
        int hh = r & 7;    int t = r >> 3;
        const float* base = g_qkv + (size_t)t * NQKV + H_*D_ + hh * D_;
        float p   = (float)pos[t];
        float ang = p * exp2f((float)dp * (-19.931568569324174f / 64.0f));
        float sn, cs; sincosf(ang, &sn, &cs);
        float x1 = base[dp], x2 = base[dp + 64];
        float y1 = x1 * cs - x2 * sn;
        float y2 = x2 * cs + x1 * sn;
        size_t o = ((size_t)t * KH_ + hh) * D_;
        split_store(g_kh, g_kl, o + dp,      y1);
        split_store(g_kh, g_kl, o + dp + 64, y2);
        return;
    }
    idx -= nk;
    if (idx >= nv) return;
    {
        int dp = idx & 63; int r = idx >> 6;
        int hh = r & 7;    int t = r >> 3;
        const float* base = g_qkv + (size_t)t * NQKV + H_*D_ + KH_*D_ + hh * D_;
        size_t o = ((size_t)t * KH_ + hh) * D_;
        split_store(g_vh, g_vl, o + dp,      base[dp]);
        split_store(g_vh, g_vl, o + dp + 64, base[dp + 64]);
    }
}

// ---------------------------------------------------------------------------
// HMMA flash attention, split-bf16 3-term QK and PV.
// 3-stage KV ring (wait_group<1>), one barrier per iteration.
// CHANGE (only one this round): K-lo / V-lo fragment loads hoisted above the
// hi-term MMAs (mirror of the R14 GEMM hoist).  Same arithmetic, same order.
// Epilogue writes hi/lo bf16 splits directly into g_Ahi/g_Alo (O-proj input).
// ---------------------------------------------------------------------------
#define AT_STRIDE 272
#define AT_SUBT   (64 * AT_STRIDE)
#define AT_STAGE  (4 * AT_SUBT)      // 69632
#define AT_NSTAGE 3
#define AT_SMEM   (AT_NSTAGE * AT_STAGE)   // 208896
#define NEGINF    (-1e30f)
#define MFLOOR    (-1e4f)

__global__ __launch_bounds__(256, 1)
void attn_mma_kernel()
{
    extern __shared__ char smraw[];
    const uint32_t sb = smem_u32(smraw);
    const int tid = threadIdx.x, wid = tid >> 5, lane = tid & 31;
    const int q0 = blockIdx.x * 128;
    const int h  = blockIdx.y;
    const int b  = blockIdx.z;
    const int kh = h >> 2;

    // ---- stage Q (hi, lo) into stage-0 region, read to registers ----
    #pragma unroll
    for (int l = 0; l < 16; l++) {
        int c    = tid + l * 256;
        int half = c >> 11;
        int rem  = c & 2047;
        int row  = rem >> 4, ch = rem & 15;
        const __nv_bfloat16* src = half ? g_ql : g_qh;
        uint32_t sa = sb + half * (128 * AT_STRIDE) + row * AT_STRIDE + ch * 16;
        CP_ASYNC16(sa, src + ((size_t)(b * S_ + q0 + row) * H_ + h) * D_ + ch * 8);
    }
    CP_COMMIT();
    cp_wait<0>();
    __syncthreads();

    uint32_t qfh[8][4], qfl[8][4];
    {
        uint32_t qa = sb + (uint32_t)(wid * 16 + (lane & 15)) * AT_STRIDE
                    + ((lane >> 4) & 1) * 16;
        #pragma unroll
        for (int ks = 0; ks < 8; ks++) {
            LDSM4(qfh[ks], qa + ks * 32);
            LDSM4(qfl[ks], qa + 128 * AT_STRIDE + ks * 32);
        }
    }
    __syncthreads();

    float o[16][4];
    #pragma unroll
    for (int i = 0; i < 16; i++)
        #pragma unroll
        for (int j = 0; j < 4; j++) o[i][j] = 0.0f;
    float m0 = MFLOOR, m1 = MFLOOR, l0 = 0.0f, l1 = 0.0f;

    int lotok = q0 - WIN_ + 1; if (lotok < 0) lotok = 0;
    const int jt0 = lotok >> 6;
    const int jt1 = (q0 + 127) >> 6;

    auto load_kv = [&](int jt, int stg) {
        int j0 = jt << 6;
        const __nv_bfloat16* srcs[4] = {g_kh, g_kl, g_vh, g_vl};
        #pragma unroll
        for (int l = 0; l < 16; l++) {
            int c   = tid + l * 256;
            int sub = c >> 10;
            int rem = c & 1023;
            int row = rem >> 4, ch = rem & 15;
            uint32_t sa = sb + stg * AT_STAGE + sub * AT_SUBT
                        + row * AT_STRIDE + ch * 16;
            CP_ASYNC16(sa, srcs[sub] +
                       ((size_t)(b * S_ + j0 + row) * KH_ + kh) * D_ + ch * 8);
        }
        CP_COMMIT();
    };

    load_kv(jt0, 0);
    if (jt0 + 1 <= jt1) load_kv(jt0 + 1, 1);

    const uint32_t kb_off = (uint32_t)((lane & 7) + ((lane >> 4) & 1) * 8) * AT_STRIDE
                          + ((lane >> 3) & 1) * 16;
    const uint32_t vt_off = (uint32_t)((lane & 7) + ((lane >> 3) & 1) * 8) * AT_STRIDE
                          + (lane >> 4) * 16;

    const int rbase0 = q0 + wid * 16 + (lane >> 2);

    for (int jt = jt0; jt <= jt1; jt++) {
        const int j0 = jt << 6;
        if (jt < jt1) cp_wait<1>(); else cp_wait<0>();
        __syncthreads();
        if (jt + 2 <= jt1) load_kv(jt + 2, (jt + 2 - jt0) % AT_NSTAGE);

        const uint32_t stgb = sb + ((jt - jt0) % AT_NSTAGE) * AT_STAGE;

        float s[8][4];
        #pragma unroll
        for (int i = 0; i < 8; i++)
            #pragma unroll
            for (int j = 0; j < 4; j++) s[i][j] = 0.0f;

        #pragma unroll
        for (int ks = 0; ks < 8; ks++) {
            #pragma unroll
            for (int nt2 = 0; nt2 < 4; nt2++) {
                uint32_t a = stgb + kb_off + (uint32_t)nt2 * (16 * AT_STRIDE) + ks * 32;
                uint32_t kf[4], kfl[4];
                LDSM4(kf,  a);               // K hi (hoisted pair)
                LDSM4(kfl, a + AT_SUBT);     // K lo
                MMA16816(s[2*nt2],   qfh[ks], kf[0], kf[1]);
                MMA16816(s[2*nt2+1], qfh[ks], kf[2], kf[3]);
                MMA16816(s[2*nt2],   qfl[ks], kf[0], kf[1]);
                MMA16816(s[2*nt2+1], qfl[ks], kf[2], kf[3]);
                MMA16816(s[2*nt2],   qfh[ks], kfl[0], kfl[1]);
                MMA16816(s[2*nt2+1], qfh[ks], kfl[2], kfl[3]);
            }
        }

        const bool needM = (j0 + 63 > q0) || ((q0 + 127 - j0) >= WIN_);
        if (needM) {
            #pragma unroll
            for (int nt = 0; nt < 8; nt++) {
                int colb = j0 + nt * 8 + 2 * (lane & 3);
                #pragma unroll
                for (int e = 0; e < 4; e++) {
                    int col = colb + (e & 1);
                    int row = rbase0 + (e >> 1) * 8;
                    if (col > row || (row - col) >= WIN_) s[nt][e] = NEGINF;
                }
            }
        }

        float t0 = NEGINF, t1 = NEGINF;
        #pragma unroll
        for (int nt = 0; nt < 8; nt++) {
            t0 = fmaxf(t0, fmaxf(s[nt][0], s[nt][1]));
            t1 = fmaxf(t1, fmaxf(s[nt][2], s[nt][3]));
        }
        t0 = fmaxf(t0, __shfl_xor_sync(0xffffffffu, t0, 1));
        t0 = fmaxf(t0, __shfl_xor_sync(0xffffffffu, t0, 2));
        t1 = fmaxf(t1, __shfl_xor_sync(0xffffffffu, t1, 1));
        t1 = fmaxf(t1, __shfl_xor_sync(0xffffffffu, t1, 2));
        float n0 = fmaxf(fmaxf(m0, t0), MFLOOR);
        float n1 = fmaxf(fmaxf(m1, t1), MFLOOR);
        float sc0 = ex2(m0 - n0);
        float sc1 = ex2(m1 - n1);
        float rs0 = 0.0f, rs1 = 0.0f;
        #pragma unroll
        for (int nt = 0; nt < 8; nt++) {
            s[nt][0] = ex2(s[nt][0] - n0); rs0 += s[nt][0];
            s[nt][1] = ex2(s[nt][1] - n0); rs0 += s[nt][1];
            s[nt][2] = ex2(s[nt][2] - n1); rs1 += s[nt][2];
            s[nt][3] = ex2(s[nt][3] - n1); rs1 += s[nt][3];
        }
        rs0 += __shfl_xor_sync(0xffffffffu, rs0, 1);
        rs0 += __shfl_xor_sync(0xffffffffu, rs0, 2);
        rs1 += __shfl_xor_sync(0xffffffffu, rs1, 1);
        rs1 += __shfl_xor_sync(0xffffffffu, rs1, 2);
        l0 = l0 * sc0 + rs0;
        l1 = l1 * sc1 + rs1;
        m0 = n0; m1 = n1;
        #pragma unroll
        for (int nt = 0; nt < 16; nt++) {
            o[nt][0] *= sc0; o[nt][1] *= sc0;
            o[nt][2] *= sc1; o[nt][3] *= sc1;
        }

        uint32_t aph[4][4], apl[4][4];
        #pragma unroll
        for (int ks = 0; ks < 4; ks++) {
            #pragma unroll
            for (int half = 0; half < 2; half++) {
                float x0 = s[2*ks + half][0], x1 = s[2*ks + half][1];
                float x2 = s[2*ks + half][2], x3 = s[2*ks + half][3];
                uint32_t h01 = pack_bf2(x0, x1);
                uint32_t h23 = pack_bf2(x2, x3);
                __nv_bfloat162 hb01, hb23;
                memcpy(&hb01, &h01, 4);
                memcpy(&hb23, &h23, 4);
                aph[ks][half * 2 + 0] = h01;
                aph[ks][half * 2 + 1] = h23;
                apl[ks][half * 2 + 0] =
                    pack_bf2(x0 - __bfloat162float(hb01.x),
                             x1 - __bfloat162float(hb01.y));
                apl[ks][half * 2 + 1] =
                    pack_bf2(x2 - __bfloat162float(hb23.x),
                             x3 - __bfloat162float(hb23.y));
            }
        }

        const uint32_t vb = stgb + 2 * AT_SUBT + vt_off;
        #pragma unroll
        for (int ks = 0; ks < 4; ks++) {
            #pragma unroll
            for (int dt2 = 0; dt2 < 8; dt2++) {
                uint32_t a = vb + (uint32_t)ks * (16 * AT_STRIDE) + dt2 * 32;
                uint32_t vf[4], vfl[4];
                LDSM4T(vf,  a);              // V hi (hoisted pair)
                LDSM4T(vfl, a + AT_SUBT);    // V lo
                MMA16816(o[2*dt2],   aph[ks], vf[0], vf[1]);
                MMA16816(o[2*dt2+1], aph[ks], vf[2], vf[3]);
                MMA16816(o[2*dt2],   apl[ks], vf[0], vf[1]);
                MMA16816(o[2*dt2+1], apl[ks], vf[2], vf[3]);
                MMA16816(o[2*dt2],   aph[ks], vfl[0], vfl[1]);
                MMA16816(o[2*dt2+1], aph[ks], vfl[2], vfl[3]);
            }
        }
        // no trailing barrier: next iteration's top barrier protects stage reuse
    }

    // ---- epilogue: normalize and write bf16 hi/lo directly (O-proj input) ----
    float i0v = 1.0f / l0, i1v = 1.0f / l1;
    size_t r0 = (size_t)(b * S_ + rbase0);
    size_t r1 = r0 + 8;
    __nv_bfloat16* hi0 = g_Ahi + r0 * HID_ + h * D_;
    __nv_bfloat16* lo0 = g_Alo + r0 * HID_ + h * D_;
    __nv_bfloat16* hi1 = g_Ahi + r1 * HID_ + h * D_;
    __nv_bfloat16* lo1 = g_Alo + r1 * HID_ + h * D_;
    #pragma unroll
    for (int nt = 0; nt < 16; nt++) {
        int colb = nt * 8 + 2 * (lane & 3);
        float x0 = o[nt][0] * i0v, x1 = o[nt][1] * i0v;
        float x2 = o[nt][2] * i1v, x3 = o[nt][3] * i1v;
        __nv_bfloat162 h01 = __floats2bfloat162_rn(x0, x1);
        __nv_bfloat162 h23 = __floats2bfloat162_rn(x2, x3);
        __nv_bfloat162 l01 = __floats2bfloat162_rn(x0 - __bfloat162float(h01.x),
                                                   x1 - __bfloat162float(h01.y));
        __nv_bfloat162 l23 = __floats2bfloat162_rn(x2 - __bfloat162float(h23.x),
                                                   x3 - __bfloat162float(h23.y));
        *reinterpret_cast<__nv_bfloat162*>(hi0 + colb) = h01;
        *reinterpret_cast<__nv_bfloat162*>(lo0 + colb) = l01;
        *reinterpret_cast<__nv_bfloat162*>(hi1 + colb) = h23;
        *reinterpret_cast<__nv_bfloat162*>(lo1 + colb) = l23;
    }
}

// ---------------------------------------------------------------------------
extern "C" void kernel_launch(void* const* d_in, const int* in_sizes, int n_in,
                              void* d_out, int out_size)
{
    const float* hidden = (const float*)d_in[0];
    const int*   pos    = (const int*)  d_in[1];
    const float* wq     = (const float*)d_in[2];
    const float* wk     = (const float*)d_in[3];
    const float* wv     = (const float*)d_in[4];
    const float* wo     = (const float*)d_in[5];
    float* out = (float*)d_out;

    float *gqkv;
    __nv_bfloat16 *ahi, *alo, *wqkvh, *wqkvl, *woh, *wol;
    cudaGetSymbolAddress((void**)&gqkv,  g_qkv);
    cudaGetSymbolAddress((void**)&ahi,   g_Ahi);
    cudaGetSymbolAddress((void**)&alo,   g_Alo);
    cudaGetSymbolAddress((void**)&wqkvh, g_Wqkvhi);
    cudaGetSymbolAddress((void**)&wqkvl, g_Wqkvlo);
    cudaGetSymbolAddress((void**)&woh,   g_Wohi);
    cudaGetSymbolAddress((void**)&wol,   g_Wolo);

    cudaFuncSetAttribute(gemm_split_kernel,
                         cudaFuncAttributeMaxDynamicSharedMemorySize, GEMM_SMEM);
    cudaFuncSetAttribute(attn_mma_kernel,
                         cudaFuncAttributeMaxDynamicSharedMemorySize, AT_SMEM);

    // ---- split inputs (5 launches) ----
    split_kernel<<<(M_TOK * HID_ / 4 + 255) / 256, 256>>>(hidden, ahi, alo,
                                                          M_TOK * HID_ / 4);
    split_T_kernel<<<dim3((H_*D_)/32,  HID_/32), dim3(32, 8)>>>(
        wq, wqkvh, wqkvl, HID_, H_*D_);
    split_T_kernel<<<dim3((KH_*D_)/32, HID_/32), dim3(32, 8)>>>(
        wk, wqkvh + (size_t)(H_*D_) * HID_, wqkvl + (size_t)(H_*D_) * HID_,
        HID_, KH_*D_);
    split_T_kernel<<<dim3((KH_*D_)/32, HID_/32), dim3(32, 8)>>>(
        wv, wqkvh + (size_t)(H_*D_ + KH_*D_) * HID_,
        wqkvl + (size_t)(H_*D_ + KH_*D_) * HID_, HID_, KH_*D_);
    split_T_kernel<<<dim3(HID_/32, (H_*D_)/32), dim3(32, 8)>>>(
        wo, woh, wol, H_*D_, HID_);

    // ---- fused QKV projection ----
    gemm_split_kernel<<<dim3(NQKV/128, M_TOK/128), 256, GEMM_SMEM>>>(
        ahi, alo, wqkvh, wqkvl, gqkv, M_TOK, NQKV, HID_);

    // ---- RoPE + attention-operand splits ----
    {
        int total = M_TOK * (H_*64 + KH_*64 + KH_*64);
        rope_split_kernel<<<(total + 255) / 256, 256>>>(pos);
    }

    // ---- attention (HMMA); writes O-proj inputs g_Ahi/g_Alo directly ----
    attn_mma_kernel<<<dim3(S_ / 128, H_, B_), 256, AT_SMEM>>>();

    // ---- output projection ----
    gemm_split_kernel<<<dim3(HID_/128, M_TOK/128), 256, GEMM_SMEM>>>(
        ahi, alo, woh, wol, out, M_TOK, HID_, H_*D_);
}

// round 16
// speedup vs baseline: 1.0072x; 1.0072x over previous
#include <cuda_runtime.h>
#include <cuda_bf16.h>
#include <math.h>
#include <stdint.h>
#include <string.h>

#define B_   2
#define S_   2048
#define HID_ 4096
#define H_   32
#define KH_  8
#define D_   128
#define WIN_ 1024
#define M_TOK (B_*S_)   // 4096 tokens
#define NQKV (H_*D_ + 2*KH_*D_)   // 6144

// ---------------------------------------------------------------------------
// Scratch (__device__ globals; no allocation allowed)
// ---------------------------------------------------------------------------
__device__ float g_qkv[M_TOK * NQKV];            // fused QKV output (fp32)

__device__ __nv_bfloat16 g_Ahi[M_TOK * HID_];    // activation splits
__device__ __nv_bfloat16 g_Alo[M_TOK * HID_];
__device__ __nv_bfloat16 g_Wqkvhi[NQKV * HID_];  // fused QKV weights [N][K]
__device__ __nv_bfloat16 g_Wqkvlo[NQKV * HID_];
__device__ __nv_bfloat16 g_Wohi[HID_ * (H_*D_)];
__device__ __nv_bfloat16 g_Wolo[HID_ * (H_*D_)];

// attention operands, bf16 hi/lo
__device__ __nv_bfloat16 g_qh[M_TOK * H_  * D_];
__device__ __nv_bfloat16 g_ql[M_TOK * H_  * D_];
__device__ __nv_bfloat16 g_kh[M_TOK * KH_ * D_];
__device__ __nv_bfloat16 g_kl[M_TOK * KH_ * D_];
__device__ __nv_bfloat16 g_vh[M_TOK * KH_ * D_];
__device__ __nv_bfloat16 g_vl[M_TOK * KH_ * D_];

// ---------------------------------------------------------------------------
// PTX helpers (family-target safe)
// ---------------------------------------------------------------------------
__device__ __forceinline__ uint32_t smem_u32(const void* p) {
    uint32_t a;
    asm("{ .reg .u64 t; cvta.to.shared.u64 t, %1; cvt.u32.u64 %0, t; }"
        : "=r"(a) : "l"(p));
    return a;
}
#define CP_ASYNC16(saddr, gaddr) \
    asm volatile("cp.async.cg.shared.global [%0], [%1], 16;" \
                 :: "r"(saddr), "l"(gaddr))
#define CP_COMMIT() asm volatile("cp.async.commit_group;" ::: "memory")
template <int N>
__device__ __forceinline__ void cp_wait() {
    asm volatile("cp.async.wait_group %0;" :: "n"(N) : "memory");
}
#define LDSM4(r, a) \
    asm volatile("ldmatrix.sync.aligned.m8n8.x4.shared.b16 {%0,%1,%2,%3}, [%4];" \
                 : "=r"((r)[0]), "=r"((r)[1]), "=r"((r)[2]), "=r"((r)[3]) : "r"(a))
#define LDSM4T(r, a) \
    asm volatile("ldmatrix.sync.aligned.m8n8.x4.trans.shared.b16 {%0,%1,%2,%3}, [%4];" \
                 : "=r"((r)[0]), "=r"((r)[1]), "=r"((r)[2]), "=r"((r)[3]) : "r"(a))
#define MMA16816(c, a, b0v, b1v) \
    asm volatile("mma.sync.aligned.m16n8k16.row.col.f32.bf16.bf16.f32 " \
                 "{%0,%1,%2,%3}, {%4,%5,%6,%7}, {%8,%9}, {%0,%1,%2,%3};" \
                 : "+f"((c)[0]), "+f"((c)[1]), "+f"((c)[2]), "+f"((c)[3]) \
                 : "r"((a)[0]), "r"((a)[1]), "r"((a)[2]), "r"((a)[3]), \
                   "r"(b0v), "r"(b1v))

__device__ __forceinline__ float ex2(float x) {
    float y;
    asm("ex2.approx.ftz.f32 %0, %1;" : "=f"(y) : "f"(x));
    return y;
}
__device__ __forceinline__ uint32_t pack_bf2(float x, float y) {
    __nv_bfloat162 h = __floats2bfloat162_rn(x, y);
    uint32_t u;
    memcpy(&u, &h, 4);
    return u;
}

// ---------------------------------------------------------------------------
// Split fp32 -> (hi, lo) bf16, same layout. n must be /4.
// ---------------------------------------------------------------------------
__global__ void split_kernel(const float* __restrict__ in,
                             __nv_bfloat16* __restrict__ hi,
                             __nv_bfloat16* __restrict__ lo, int n4)
{
    int i = blockIdx.x * blockDim.x + threadIdx.x;
    if (i >= n4) return;
    float4 v = reinterpret_cast<const float4*>(in)[i];
    __nv_bfloat16 h0 = __float2bfloat16_rn(v.x);
    __nv_bfloat16 h1 = __float2bfloat16_rn(v.y);
    __nv_bfloat16 h2 = __float2bfloat16_rn(v.z);
    __nv_bfloat16 h3 = __float2bfloat16_rn(v.w);
    __nv_bfloat162 hp0; hp0.x = h0; hp0.y = h1;
    __nv_bfloat162 hp1; hp1.x = h2; hp1.y = h3;
    reinterpret_cast<__nv_bfloat162*>(hi)[i * 2]     = hp0;
    reinterpret_cast<__nv_bfloat162*>(hi)[i * 2 + 1] = hp1;
    __nv_bfloat162 lp0, lp1;
    lp0.x = __float2bfloat16_rn(v.x - __bfloat162float(h0));
    lp0.y = __float2bfloat16_rn(v.y - __bfloat162float(h1));
    lp1.x = __float2bfloat16_rn(v.z - __bfloat162float(h2));
    lp1.y = __float2bfloat16_rn(v.w - __bfloat162float(h3));
    reinterpret_cast<__nv_bfloat162*>(lo)[i * 2]     = lp0;
    reinterpret_cast<__nv_bfloat162*>(lo)[i * 2 + 1] = lp1;
}

// ---------------------------------------------------------------------------
// Split + transpose: w[K,N] fp32 -> hi/lo[N,K] bf16.
// ---------------------------------------------------------------------------
__global__ void split_T_kernel(const float* __restrict__ w,
                               __nv_bfloat16* __restrict__ hi,
                               __nv_bfloat16* __restrict__ lo, int K, int N)
{
    __shared__ float t[32][33];
    int k0 = blockIdx.y * 32, n0 = blockIdx.x * 32;
    int tx = threadIdx.x, ty = threadIdx.y;
    #pragma unroll
    for (int r = 0; r < 4; r++)
        t[ty + 8 * r][tx] = w[(size_t)(k0 + ty + 8 * r) * N + n0 + tx];
    __syncthreads();
    #pragma unroll
    for (int r = 0; r < 4; r++) {
        int n = ty + 8 * r;
        float x = t[tx][n];
        __nv_bfloat16 h = __float2bfloat16_rn(x);
        float rem = x - __bfloat162float(h);
        size_t o = (size_t)(n0 + n) * K + k0 + tx;
        hi[o] = h;
        lo[o] = __float2bfloat16_rn(rem);
    }
}

// ---------------------------------------------------------------------------
// Split-bf16 GEMM via mma.sync (HMMA): C = Ahi*Whi + Ahi*Wlo + Alo*Whi
// from 4 staged tiles per BK=32 chunk. 128x128 tile, 3-stage cp.async ring,
// XOR-swizzled 64B rows, one barrier/iter, 96KB smem, 2 CTAs/SM.
// bl LDSM hoisted above term-1 MMAs (R14 — measured win).
// ---------------------------------------------------------------------------
#define G_TILE     8192
#define G_STAGE    (4 * G_TILE)
#define G_NSTAGE   3
#define GEMM_SMEM  (G_NSTAGE * G_STAGE)   // 98304

__global__ __launch_bounds__(256, 2)
void gemm_split_kernel(const __nv_bfloat16* __restrict__ Ahi,
                       const __nv_bfloat16* __restrict__ Alo,
                       const __nv_bfloat16* __restrict__ Whi,
                       const __nv_bfloat16* __restrict__ Wlo,
                       float* __restrict__ C, int M, int N, int K)
{
    extern __shared__ char smc[];
    const uint32_t sbase = smem_u32(smc);

    const int tid  = threadIdx.x;
    const int wid  = tid >> 5;
    const int lane = tid & 31;
    const int wm   = wid >> 2;
    const int wn   = wid & 3;
    const int m0   = blockIdx.y * 128;
    const int n0   = blockIdx.x * 128;

    const int nk = K >> 5;

    float acc[4][4][4];
    #pragma unroll
    for (int i = 0; i < 4; i++)
        #pragma unroll
        for (int j = 0; j < 4; j++)
            #pragma unroll
            for (int q = 0; q < 4; q++) acc[i][j][q] = 0.0f;

    auto load_stage = [&](int kt, int buf) {
        int k0 = kt << 5;
        uint32_t sb0 = sbase + buf * G_STAGE;
        #pragma unroll
        for (int l = 0; l < 8; l++) {
            int c    = tid + l * 256;
            int tile = c >> 9;
            int rem  = c & 511;
            int row  = rem >> 2, ch = rem & 3;
            int chs  = ch ^ ((row >> 1) & 3);
            const __nv_bfloat16* src;
            int rbase;
            if (tile == 0)      { src = Ahi; rbase = m0; }
            else if (tile == 1) { src = Alo; rbase = m0; }
            else if (tile == 2) { src = Whi; rbase = n0; }
            else                { src = Wlo; rbase = n0; }
            CP_ASYNC16(sb0 + tile * G_TILE + row * 64 + chs * 16,
                       src + (size_t)(rbase + row) * K + k0 + ch * 8);
        }
        CP_COMMIT();
    };

    load_stage(0, 0);
    if (nk > 1) load_stage(1, 1);

    const int      xf       = (lane >> 1) & 3;
    const uint32_t a_rowoff = (uint32_t)(wm * 64 + (lane & 15)) * 64;
    const uint32_t b_rowoff = (uint32_t)(wn * 32 + (lane & 7)
                                         + ((lane >> 4) & 1) * 8) * 64;
    const int ca_base = lane >> 4;
    const int cb_base = (lane >> 3) & 1;

    for (int kt = 0; kt < nk; kt++) {
        if (kt + 1 < nk) cp_wait<1>(); else cp_wait<0>();
        __syncthreads();
        if (kt + 2 < nk) load_stage(kt + 2, (kt + 2) % G_NSTAGE);

        const uint32_t stg = sbase + (kt % G_NSTAGE) * G_STAGE;
        const uint32_t aAh = stg + a_rowoff;
        const uint32_t aAl = aAh + G_TILE;
        const uint32_t aWh = stg + 2 * G_TILE + b_rowoff;
        const uint32_t aWl = aWh + G_TILE;

        #pragma unroll
        for (int ks = 0; ks < 2; ks++) {
            const uint32_t ao = (uint32_t)(((ks * 2 + ca_base) ^ xf) * 16);
            const uint32_t bo = (uint32_t)(((ks * 2 + cb_base) ^ xf) * 16);
            uint32_t ah[4][4];
            #pragma unroll
            for (int mt = 0; mt < 4; mt++)
                LDSM4(ah[mt], aAh + mt * 1024 + ao);
            uint32_t bh[2][4];
            #pragma unroll
            for (int nt2 = 0; nt2 < 2; nt2++)
                LDSM4(bh[nt2], aWh + nt2 * 1024 + bo);
            uint32_t bl[2][4];
            #pragma unroll
            for (int nt2 = 0; nt2 < 2; nt2++)
                LDSM4(bl[nt2], aWl + nt2 * 1024 + bo);
            // term 1: Ahi * Whi
            #pragma unroll
            for (int mt = 0; mt < 4; mt++)
                #pragma unroll
                for (int nt = 0; nt < 4; nt++)
                    MMA16816(acc[mt][nt], ah[mt],
                             bh[nt >> 1][(nt & 1) * 2],
                             bh[nt >> 1][(nt & 1) * 2 + 1]);
            // term 2: Ahi * Wlo
            #pragma unroll
            for (int mt = 0; mt < 4; mt++)
                #pragma unroll
                for (int nt = 0; nt < 4; nt++)
                    MMA16816(acc[mt][nt], ah[mt],
                             bl[nt >> 1][(nt & 1) * 2],
                             bl[nt >> 1][(nt & 1) * 2 + 1]);
            // term 3: Alo * Whi
            {
                uint32_t al[4][4];
                #pragma unroll
                for (int mt = 0; mt < 4; mt++)
                    LDSM4(al[mt], aAl + mt * 1024 + ao);
                #pragma unroll
                for (int mt = 0; mt < 4; mt++)
                    #pragma unroll
                    for (int nt = 0; nt < 4; nt++)
                        MMA16816(acc[mt][nt], al[mt],
                                 bh[nt >> 1][(nt & 1) * 2],
                                 bh[nt >> 1][(nt & 1) * 2 + 1]);
            }
        }
    }

    #pragma unroll
    for (int mt = 0; mt < 4; mt++) {
        int row0 = m0 + wm * 64 + mt * 16 + (lane >> 2);
        #pragma unroll
        for (int nt = 0; nt < 4; nt++) {
            int col = n0 + wn * 32 + nt * 8 + 2 * (lane & 3);
            float2 v0 = make_float2(acc[mt][nt][0], acc[mt][nt][1]);
            float2 v1 = make_float2(acc[mt][nt][2], acc[mt][nt][3]);
            *reinterpret_cast<float2*>(&C[(size_t)row0 * N + col])       = v0;
            *reinterpret_cast<float2*>(&C[(size_t)(row0 + 8) * N + col]) = v1;
        }
    }
}

// ---------------------------------------------------------------------------
// RoPE + split from fused g_qkv.
// CHANGE (only one this round): one thread per (token, dim-pair) computes
// sincos ONCE and loops over all 32 Q heads + 8 K heads (40x fewer sincos).
// V handled by a separate index range (no sincos).  Identical per-element
// formulas -> bit-identical outputs.
// ---------------------------------------------------------------------------
__device__ __forceinline__ void split_store(__nv_bfloat16* hi, __nv_bfloat16* lo,
                                            size_t o, float x) {
    __nv_bfloat16 h = __float2bfloat16_rn(x);
    hi[o] = h;
    lo[o] = __float2bfloat16_rn(x - __bfloat162float(h));
}

__global__ void rope_split_kernel(const int* __restrict__ pos)
{
    const float QS = 0.08838834764831845f * 1.4426950408889634f; // 1/sqrt(128)*log2(e)
    int idx = blockIdx.x * blockDim.x + threadIdx.x;
    const int nqk = M_TOK * 64;              // one thread per (token, dp)
    const int nv  = M_TOK * KH_ * 64;

    if (idx < nqk) {
        int dp = idx & 63;
        int t  = idx >> 6;
        float p   = (float)pos[t];
        float ang = p * exp2f((float)dp * (-19.931568569324174f / 64.0f));
        float sn, cs;
        sincosf(ang, &sn, &cs);
        const float* tb = g_qkv + (size_t)t * NQKV;

        // Q heads: rope + scale + split
        #pragma unroll 4
        for (int hh = 0; hh < H_; hh++) {
            const float* base = tb + hh * D_;
            float x1 = base[dp], x2 = base[dp + 64];
            float y1 = (x1 * cs - x2 * sn) * QS;
            float y2 = (x2 * cs + x1 * sn) * QS;
            size_t o = ((size_t)t * H_ + hh) * D_;
            split_store(g_qh, g_ql, o + dp,      y1);
            split_store(g_qh, g_ql, o + dp + 64, y2);
        }
        // K heads: rope + split
        #pragma unroll
        for (int hh = 0; hh < KH_; hh++) {
            const float* base = tb + H_*D_ + hh * D_;
            float x1 = base[dp], x2 = base[dp + 64];
            float y1 = x1 * cs - x2 * sn;
            float y2 = x2 * cs + x1 * sn;
            size_t o = ((size_t)t * KH_ + hh) * D_;
            split_store(g_kh, g_kl, o + dp,      y1);
            split_store(g_kh, g_kl, o + dp + 64, y2);
        }
        return;
    }
    idx -= nqk;
    if (idx >= nv) return;
    {
        int dp = idx & 63; int r = idx >> 6;
        int hh = r & 7;    int t = r >> 3;
        const float* base = g_qkv + (size_t)t * NQKV + H_*D_ + KH_*D_ + hh * D_;
        size_t o = ((size_t)t * KH_ + hh) * D_;
        split_store(g_vh, g_vl, o + dp,      base[dp]);
        split_store(g_vh, g_vl, o + dp + 64, base[dp + 64]);
    }
}

// ---------------------------------------------------------------------------
// HMMA flash attention, split-bf16 3-term QK and PV.  (R14 verbatim — best.)
// 3-stage KV ring (wait_group<1>), one barrier per iteration.
// Epilogue writes hi/lo bf16 splits directly into g_Ahi/g_Alo (O-proj input).
// ---------------------------------------------------------------------------
#define AT_STRIDE 272
#define AT_SUBT   (64 * AT_STRIDE)
#define AT_STAGE  (4 * AT_SUBT)      // 69632
#define AT_NSTAGE 3
#define AT_SMEM   (AT_NSTAGE * AT_STAGE)   // 208896
#define NEGINF    (-1e30f)
#define MFLOOR    (-1e4f)

__global__ __launch_bounds__(256, 1)
void attn_mma_kernel()
{
    extern __shared__ char smraw[];
    const uint32_t sb = smem_u32(smraw);
    const int tid = threadIdx.x, wid = tid >> 5, lane = tid & 31;
    const int q0 = blockIdx.x * 128;
    const int h  = blockIdx.y;
    const int b  = blockIdx.z;
    const int kh = h >> 2;

    // ---- stage Q (hi, lo) into stage-0 region, read to registers ----
    #pragma unroll
    for (int l = 0; l < 16; l++) {
        int c    = tid + l * 256;
        int half = c >> 11;
        int rem  = c & 2047;
        int row  = rem >> 4, ch = rem & 15;
        const __nv_bfloat16* src = half ? g_ql : g_qh;
        uint32_t sa = sb + half * (128 * AT_STRIDE) + row * AT_STRIDE + ch * 16;
        CP_ASYNC16(sa, src + ((size_t)(b * S_ + q0 + row) * H_ + h) * D_ + ch * 8);
    }
    CP_COMMIT();
    cp_wait<0>();
    __syncthreads();

    uint32_t qfh[8][4], qfl[8][4];
    {
        uint32_t qa = sb + (uint32_t)(wid * 16 + (lane & 15)) * AT_STRIDE
                    + ((lane >> 4) & 1) * 16;
        #pragma unroll
        for (int ks = 0; ks < 8; ks++) {
            LDSM4(qfh[ks], qa + ks * 32);
            LDSM4(qfl[ks], qa + 128 * AT_STRIDE + ks * 32);
        }
    }
    __syncthreads();

    float o[16][4];
    #pragma unroll
    for (int i = 0; i < 16; i++)
        #pragma unroll
        for (int j = 0; j < 4; j++) o[i][j] = 0.0f;
    float m0 = MFLOOR, m1 = MFLOOR, l0 = 0.0f, l1 = 0.0f;

    int lotok = q0 - WIN_ + 1; if (lotok < 0) lotok = 0;
    const int jt0 = lotok >> 6;
    const int jt1 = (q0 + 127) >> 6;

    auto load_kv = [&](int jt, int stg) {
        int j0 = jt << 6;
        const __nv_bfloat16* srcs[4] = {g_kh, g_kl, g_vh, g_vl};
        #pragma unroll
        for (int l = 0; l < 16; l++) {
            int c   = tid + l * 256;
            int sub = c >> 10;
            int rem = c & 1023;
            int row = rem >> 4, ch = rem & 15;
            uint32_t sa = sb + stg * AT_STAGE + sub * AT_SUBT
                        + row * AT_STRIDE + ch * 16;
            CP_ASYNC16(sa, srcs[sub] +
                       ((size_t)(b * S_ + j0 + row) * KH_ + kh) * D_ + ch * 8);
        }
        CP_COMMIT();
    };

    load_kv(jt0, 0);
    if (jt0 + 1 <= jt1) load_kv(jt0 + 1, 1);

    const uint32_t kb_off = (uint32_t)((lane & 7) + ((lane >> 4) & 1) * 8) * AT_STRIDE
                          + ((lane >> 3) & 1) * 16;
    const uint32_t vt_off = (uint32_t)((lane & 7) + ((lane >> 3) & 1) * 8) * AT_STRIDE
                          + (lane >> 4) * 16;

    const int rbase0 = q0 + wid * 16 + (lane >> 2);

    for (int jt = jt0; jt <= jt1; jt++) {
        const int j0 = jt << 6;
        if (jt < jt1) cp_wait<1>(); else cp_wait<0>();
        __syncthreads();
        if (jt + 2 <= jt1) load_kv(jt + 2, (jt + 2 - jt0) % AT_NSTAGE);

        const uint32_t stgb = sb + ((jt - jt0) % AT_NSTAGE) * AT_STAGE;

        float s[8][4];
        #pragma unroll
        for (int i = 0; i < 8; i++)
            #pragma unroll
            for (int j = 0; j < 4; j++) s[i][j] = 0.0f;

        #pragma unroll
        for (int ks = 0; ks < 8; ks++) {
            #pragma unroll
            for (int nt2 = 0; nt2 < 4; nt2++) {
                uint32_t a = stgb + kb_off + (uint32_t)nt2 * (16 * AT_STRIDE) + ks * 32;
                uint32_t kf[4];
                LDSM4(kf, a);
                MMA16816(s[2*nt2],   qfh[ks], kf[0], kf[1]);
                MMA16816(s[2*nt2+1], qfh[ks], kf[2], kf[3]);
                MMA16816(s[2*nt2],   qfl[ks], kf[0], kf[1]);
                MMA16816(s[2*nt2+1], qfl[ks], kf[2], kf[3]);
                LDSM4(kf, a + AT_SUBT);
                MMA16816(s[2*nt2],   qfh[ks], kf[0], kf[1]);
                MMA16816(s[2*nt2+1], qfh[ks], kf[2], kf[3]);
            }
        }

        const bool needM = (j0 + 63 > q0) || ((q0 + 127 - j0) >= WIN_);
        if (needM) {
            #pragma unroll
            for (int nt = 0; nt < 8; nt++) {
                int colb = j0 + nt * 8 + 2 * (lane & 3);
                #pragma unroll
                for (int e = 0; e < 4; e++) {
                    int col = colb + (e & 1);
                    int row = rbase0 + (e >> 1) * 8;
                    if (col > row || (row - col) >= WIN_) s[nt][e] = NEGINF;
                }
            }
        }

        float t0 = NEGINF, t1 = NEGINF;
        #pragma unroll
        for (int nt = 0; nt < 8; nt++) {
            t0 = fmaxf(t0, fmaxf(s[nt][0], s[nt][1]));
            t1 = fmaxf(t1, fmaxf(s[nt][2], s[nt][3]));
        }
        t0 = fmaxf(t0, __shfl_xor_sync(0xffffffffu, t0, 1));
        t0 = fmaxf(t0, __shfl_xor_sync(0xffffffffu, t0, 2));
        t1 = fmaxf(t1, __shfl_xor_sync(0xffffffffu, t1, 1));
        t1 = fmaxf(t1, __shfl_xor_sync(0xffffffffu, t1, 2));
        float n0 = fmaxf(fmaxf(m0, t0), MFLOOR);
        float n1 = fmaxf(fmaxf(m1, t1), MFLOOR);
        float sc0 = ex2(m0 - n0);
        float sc1 = ex2(m1 - n1);
        float rs0 = 0.0f, rs1 = 0.0f;
        #pragma unroll
        for (int nt = 0; nt < 8; nt++) {
            s[nt][0] = ex2(s[nt][0] - n0); rs0 += s[nt][0];
            s[nt][1] = ex2(s[nt][1] - n0); rs0 += s[nt][1];
            s[nt][2] = ex2(s[nt][2] - n1); rs1 += s[nt][2];
            s[nt][3] = ex2(s[nt][3] - n1); rs1 += s[nt][3];
        }
        rs0 += __shfl_xor_sync(0xffffffffu, rs0, 1);
        rs0 += __shfl_xor_sync(0xffffffffu, rs0, 2);
        rs1 += __shfl_xor_sync(0xffffffffu, rs1, 1);
        rs1 += __shfl_xor_sync(0xffffffffu, rs1, 2);
        l0 = l0 * sc0 + rs0;
        l1 = l1 * sc1 + rs1;
        m0 = n0; m1 = n1;
        #pragma unroll
        for (int nt = 0; nt < 16; nt++) {
            o[nt][0] *= sc0; o[nt][1] *= sc0;
            o[nt][2] *= sc1; o[nt][3] *= sc1;
        }

        uint32_t aph[4][4], apl[4][4];
        #pragma unroll
        for (int ks = 0; ks < 4; ks++) {
            #pragma unroll
            for (int half = 0; half < 2; half++) {
                float x0 = s[2*ks + half][0], x1 = s[2*ks + half][1];
                float x2 = s[2*ks + half][2], x3 = s[2*ks + half][3];
                uint32_t h01 = pack_bf2(x0, x1);
                uint32_t h23 = pack_bf2(x2, x3);
                __nv_bfloat162 hb01, hb23;
                memcpy(&hb01, &h01, 4);
                memcpy(&hb23, &h23, 4);
                aph[ks][half * 2 + 0] = h01;
                aph[ks][half * 2 + 1] = h23;
                apl[ks][half * 2 + 0] =
                    pack_bf2(x0 - __bfloat162float(hb01.x),
                             x1 - __bfloat162float(hb01.y));
                apl[ks][half * 2 + 1] =
                    pack_bf2(x2 - __bfloat162float(hb23.x),
                             x3 - __bfloat162float(hb23.y));
            }
        }

        const uint32_t vb = stgb + 2 * AT_SUBT + vt_off;
        #pragma unroll
        for (int ks = 0; ks < 4; ks++) {
            #pragma unroll
            for (int dt2 = 0; dt2 < 8; dt2++) {
                uint32_t a = vb + (uint32_t)ks * (16 * AT_STRIDE) + dt2 * 32;
                uint32_t vf[4];
                LDSM4T(vf, a);
                MMA16816(o[2*dt2],   aph[ks], vf[0], vf[1]);
                MMA16816(o[2*dt2+1], aph[ks], vf[2], vf[3]);
                MMA16816(o[2*dt2],   apl[ks], vf[0], vf[1]);
                MMA16816(o[2*dt2+1], apl[ks], vf[2], vf[3]);
                LDSM4T(vf, a + AT_SUBT);
                MMA16816(o[2*dt2],   aph[ks], vf[0], vf[1]);
                MMA16816(o[2*dt2+1], aph[ks], vf[2], vf[3]);
            }
        }
        // no trailing barrier: next iteration's top barrier protects stage reuse
    }

    // ---- epilogue: normalize and write bf16 hi/lo directly (O-proj input) ----
    float i0v = 1.0f / l0, i1v = 1.0f / l1;
    size_t r0 = (size_t)(b * S_ + rbase0);
    size_t r1 = r0 + 8;
    __nv_bfloat16* hi0 = g_Ahi + r0 * HID_ + h * D_;
    __nv_bfloat16* lo0 = g_Alo + r0 * HID_ + h * D_;
    __nv_bfloat16* hi1 = g_Ahi + r1 * HID_ + h * D_;
    __nv_bfloat16* lo1 = g_Alo + r1 * HID_ + h * D_;
    #pragma unroll
    for (int nt = 0; nt < 16; nt++) {
        int colb = nt * 8 + 2 * (lane & 3);
        float x0 = o[nt][0] * i0v, x1 = o[nt][1] * i0v;
        float x2 = o[nt][2] * i1v, x3 = o[nt][3] * i1v;
        __nv_bfloat162 h01 = __floats2bfloat162_rn(x0, x1);
        __nv_bfloat162 h23 = __floats2bfloat162_rn(x2, x3);
        __nv_bfloat162 l01 = __floats2bfloat162_rn(x0 - __bfloat162float(h01.x),
                                                   x1 - __bfloat162float(h01.y));
        __nv_bfloat162 l23 = __floats2bfloat162_rn(x2 - __bfloat162float(h23.x),
                                                   x3 - __bfloat162float(h23.y));
        *reinterpret_cast<__nv_bfloat162*>(hi0 + colb) = h01;
        *reinterpret_cast<__nv_bfloat162*>(lo0 + colb) = l01;
        *reinterpret_cast<__nv_bfloat162*>(hi1 + colb) = h23;
        *reinterpret_cast<__nv_bfloat162*>(lo1 + colb) = l23;
    }
}

// ---------------------------------------------------------------------------
extern "C" void kernel_launch(void* const* d_in, const int* in_sizes, int n_in,
                              void* d_out, int out_size)
{
    const float* hidden = (const float*)d_in[0];
    const int*   pos    = (const int*)  d_in[1];
    const float* wq     = (const float*)d_in[2];
    const float* wk     = (const float*)d_in[3];
    const float* wv     = (const float*)d_in[4];
    const float* wo     = (const float*)d_in[5];
    float* out = (float*)d_out;

    float *gqkv;
    __nv_bfloat16 *ahi, *alo, *wqkvh, *wqkvl, *woh, *wol;
    cudaGetSymbolAddress((void**)&gqkv,  g_qkv);
    cudaGetSymbolAddress((void**)&ahi,   g_Ahi);
    cudaGetSymbolAddress((void**)&alo,   g_Alo);
    cudaGetSymbolAddress((void**)&wqkvh, g_Wqkvhi);
    cudaGetSymbolAddress((void**)&wqkvl, g_Wqkvlo);
    cudaGetSymbolAddress((void**)&woh,   g_Wohi);
    cudaGetSymbolAddress((void**)&wol,   g_Wolo);

    cudaFuncSetAttribute(gemm_split_kernel,
                         cudaFuncAttributeMaxDynamicSharedMemorySize, GEMM_SMEM);
    cudaFuncSetAttribute(attn_mma_kernel,
                         cudaFuncAttributeMaxDynamicSharedMemorySize, AT_SMEM);

    // ---- split inputs (5 launches) ----
    split_kernel<<<(M_TOK * HID_ / 4 + 255) / 256, 256>>>(hidden, ahi, alo,
                                                          M_TOK * HID_ / 4);
    split_T_kernel<<<dim3((H_*D_)/32,  HID_/32), dim3(32, 8)>>>(
        wq, wqkvh, wqkvl, HID_, H_*D_);
    split_T_kernel<<<dim3((KH_*D_)/32, HID_/32), dim3(32, 8)>>>(
        wk, wqkvh + (size_t)(H_*D_) * HID_, wqkvl + (size_t)(H_*D_) * HID_,
        HID_, KH_*D_);
    split_T_kernel<<<dim3((KH_*D_)/32, HID_/32), dim3(32, 8)>>>(
        wv, wqkvh + (size_t)(H_*D_ + KH_*D_) * HID_,
        wqkvl + (size_t)(H_*D_ + KH_*D_) * HID_, HID_, KH_*D_);
    split_T_kernel<<<dim3(HID_/32, (H_*D_)/32), dim3(32, 8)>>>(
        wo, woh, wol, H_*D_, HID_);

    // ---- fused QKV projection ----
    gemm_split_kernel<<<dim3(NQKV/128, M_TOK/128), 256, GEMM_SMEM>>>(
        ahi, alo, wqkvh, wqkvl, gqkv, M_TOK, NQKV, HID_);

    // ---- RoPE + attention-operand splits (sincos amortized over heads) ----
    {
        int total = M_TOK * 64 + M_TOK * KH_ * 64;
        rope_split_kernel<<<(total + 255) / 256, 256>>>(pos);
    }

    // ---- attention (HMMA); writes O-proj inputs g_Ahi/g_Alo directly ----
    attn_mma_kernel<<<dim3(S_ / 128, H_, B_), 256, AT_SMEM>>>();

    // ---- output projection ----
    gemm_split_kernel<<<dim3(HID_/128, M_TOK/128), 256, GEMM_SMEM>>>(
        ahi, alo, woh, wol, out, M_TOK, HID_, H_*D_);
}

// round 17
// speedup vs baseline: 1.0116x; 1.0044x over previous
#include <cuda_runtime.h>
#include <cuda_bf16.h>
#include <math.h>
#include <stdint.h>
#include <string.h>

#define B_   2
#define S_   2048
#define HID_ 4096
#define H_   32
#define KH_  8
#define D_   128
#define WIN_ 1024
#define M_TOK (B_*S_)   // 4096 tokens
#define NQKV (H_*D_ + 2*KH_*D_)   // 6144

// ---------------------------------------------------------------------------
// Scratch (__device__ globals; no allocation allowed)
// ---------------------------------------------------------------------------
__device__ float g_qkv[M_TOK * NQKV];            // fused QKV output (fp32)

__device__ __nv_bfloat16 g_Ahi[M_TOK * HID_];    // activation splits
__device__ __nv_bfloat16 g_Alo[M_TOK * HID_];
__device__ __nv_bfloat16 g_Wqkvhi[NQKV * HID_];  // fused QKV weights [N][K]
__device__ __nv_bfloat16 g_Wqkvlo[NQKV * HID_];
__device__ __nv_bfloat16 g_Wohi[HID_ * (H_*D_)];
__device__ __nv_bfloat16 g_Wolo[HID_ * (H_*D_)];

// attention operands, bf16 hi/lo
__device__ __nv_bfloat16 g_qh[M_TOK * H_  * D_];
__device__ __nv_bfloat16 g_ql[M_TOK * H_  * D_];
__device__ __nv_bfloat16 g_kh[M_TOK * KH_ * D_];
__device__ __nv_bfloat16 g_kl[M_TOK * KH_ * D_];
__device__ __nv_bfloat16 g_vh[M_TOK * KH_ * D_];
__device__ __nv_bfloat16 g_vl[M_TOK * KH_ * D_];

// ---------------------------------------------------------------------------
// PTX helpers (family-target safe)
// ---------------------------------------------------------------------------
__device__ __forceinline__ uint32_t smem_u32(const void* p) {
    uint32_t a;
    asm("{ .reg .u64 t; cvta.to.shared.u64 t, %1; cvt.u32.u64 %0, t; }"
        : "=r"(a) : "l"(p));
    return a;
}
#define CP_ASYNC16(saddr, gaddr) \
    asm volatile("cp.async.cg.shared.global [%0], [%1], 16;" \
                 :: "r"(saddr), "l"(gaddr))
#define CP_COMMIT() asm volatile("cp.async.commit_group;" ::: "memory")
template <int N>
__device__ __forceinline__ void cp_wait() {
    asm volatile("cp.async.wait_group %0;" :: "n"(N) : "memory");
}
#define LDSM4(r, a) \
    asm volatile("ldmatrix.sync.aligned.m8n8.x4.shared.b16 {%0,%1,%2,%3}, [%4];" \
                 : "=r"((r)[0]), "=r"((r)[1]), "=r"((r)[2]), "=r"((r)[3]) : "r"(a))
#define LDSM4T(r, a) \
    asm volatile("ldmatrix.sync.aligned.m8n8.x4.trans.shared.b16 {%0,%1,%2,%3}, [%4];" \
                 : "=r"((r)[0]), "=r"((r)[1]), "=r"((r)[2]), "=r"((r)[3]) : "r"(a))
#define MMA16816(c, a, b0v, b1v) \
    asm volatile("mma.sync.aligned.m16n8k16.row.col.f32.bf16.bf16.f32 " \
                 "{%0,%1,%2,%3}, {%4,%5,%6,%7}, {%8,%9}, {%0,%1,%2,%3};" \
                 : "+f"((c)[0]), "+f"((c)[1]), "+f"((c)[2]), "+f"((c)[3]) \
                 : "r"((a)[0]), "r"((a)[1]), "r"((a)[2]), "r"((a)[3]), \
                   "r"(b0v), "r"(b1v))

__device__ __forceinline__ float ex2(float x) {
    float y;
    asm("ex2.approx.ftz.f32 %0, %1;" : "=f"(y) : "f"(x));
    return y;
}
__device__ __forceinline__ uint32_t pack_bf2(float x, float y) {
    __nv_bfloat162 h = __floats2bfloat162_rn(x, y);
    uint32_t u;
    memcpy(&u, &h, 4);
    return u;
}

// ---------------------------------------------------------------------------
// Split fp32 -> (hi, lo) bf16, same layout. n must be /4.
// ---------------------------------------------------------------------------
__global__ void split_kernel(const float* __restrict__ in,
                             __nv_bfloat16* __restrict__ hi,
                             __nv_bfloat16* __restrict__ lo, int n4)
{
    int i = blockIdx.x * blockDim.x + threadIdx.x;
    if (i >= n4) return;
    float4 v = reinterpret_cast<const float4*>(in)[i];
    __nv_bfloat16 h0 = __float2bfloat16_rn(v.x);
    __nv_bfloat16 h1 = __float2bfloat16_rn(v.y);
    __nv_bfloat16 h2 = __float2bfloat16_rn(v.z);
    __nv_bfloat16 h3 = __float2bfloat16_rn(v.w);
    __nv_bfloat162 hp0; hp0.x = h0; hp0.y = h1;
    __nv_bfloat162 hp1; hp1.x = h2; hp1.y = h3;
    reinterpret_cast<__nv_bfloat162*>(hi)[i * 2]     = hp0;
    reinterpret_cast<__nv_bfloat162*>(hi)[i * 2 + 1] = hp1;
    __nv_bfloat162 lp0, lp1;
    lp0.x = __float2bfloat16_rn(v.x - __bfloat162float(h0));
    lp0.y = __float2bfloat16_rn(v.y - __bfloat162float(h1));
    lp1.x = __float2bfloat16_rn(v.z - __bfloat162float(h2));
    lp1.y = __float2bfloat16_rn(v.w - __bfloat162float(h3));
    reinterpret_cast<__nv_bfloat162*>(lo)[i * 2]     = lp0;
    reinterpret_cast<__nv_bfloat162*>(lo)[i * 2 + 1] = lp1;
}

// ---------------------------------------------------------------------------
// Split + transpose: w[K,N] fp32 -> hi/lo[N,K] bf16.
// CHANGE (only one this round): 64(K)x32(N) tile, flat 256-thread block,
// paired __nv_bfloat162 stores -> 128B-coalesced writes per warp.
// Per-element conversion math identical -> bit-identical outputs.
// Requires K % 64 == 0, N % 32 == 0 (holds for all four weights).
// ---------------------------------------------------------------------------
__global__ __launch_bounds__(256)
void split_T_kernel(const float* __restrict__ w,
                    __nv_bfloat16* __restrict__ hi,
                    __nv_bfloat16* __restrict__ lo, int K, int N)
{
    __shared__ float t[64][33];
    int k0 = blockIdx.y * 64, n0 = blockIdx.x * 32;
    const int tid = threadIdx.x;
    const int tx = tid & 31, ty = tid >> 5;   // ty 0..7

    // load 64 rows x 32 cols (each row-load is 128B coalesced)
    #pragma unroll
    for (int r = 0; r < 8; r++) {
        int k = ty + 8 * r;                   // 0..63
        t[k][tx] = w[(size_t)(k0 + k) * N + n0 + tx];
    }
    __syncthreads();

    // write: lane tx packs k-pair (2tx, 2tx+1) for n = ty + 8r
    #pragma unroll
    for (int r = 0; r < 4; r++) {
        int n = ty + 8 * r;                   // 0..31
        float x0 = t[2 * tx][n];
        float x1 = t[2 * tx + 1][n];
        __nv_bfloat16 h0 = __float2bfloat16_rn(x0);
        __nv_bfloat16 h1 = __float2bfloat16_rn(x1);
        __nv_bfloat162 hp; hp.x = h0; hp.y = h1;
        __nv_bfloat162 lp;
        lp.x = __float2bfloat16_rn(x0 - __bfloat162float(h0));
        lp.y = __float2bfloat16_rn(x1 - __bfloat162float(h1));
        size_t o2 = (((size_t)(n0 + n) * K) + k0) / 2 + tx;  // bf162 index
        reinterpret_cast<__nv_bfloat162*>(hi)[o2] = hp;
        reinterpret_cast<__nv_bfloat162*>(lo)[o2] = lp;
    }
}

// ---------------------------------------------------------------------------
// Split-bf16 GEMM via mma.sync (HMMA): C = Ahi*Whi + Ahi*Wlo + Alo*Whi
// from 4 staged tiles per BK=32 chunk. 128x128 tile, 3-stage cp.async ring,
// XOR-swizzled 64B rows, one barrier/iter, 96KB smem, 2 CTAs/SM.
// bl LDSM hoisted above term-1 MMAs (R14 — measured win).
// ---------------------------------------------------------------------------
#define G_TILE     8192
#define G_STAGE    (4 * G_TILE)
#define G_NSTAGE   3
#define GEMM_SMEM  (G_NSTAGE * G_STAGE)   // 98304

__global__ __launch_bounds__(256, 2)
void gemm_split_kernel(const __nv_bfloat16* __restrict__ Ahi,
                       const __nv_bfloat16* __restrict__ Alo,
                       const __nv_bfloat16* __restrict__ Whi,
                       const __nv_bfloat16* __restrict__ Wlo,
                       float* __restrict__ C, int M, int N, int K)
{
    extern __shared__ char smc[];
    const uint32_t sbase = smem_u32(smc);

    const int tid  = threadIdx.x;
    const int wid  = tid >> 5;
    const int lane = tid & 31;
    const int wm   = wid >> 2;
    const int wn   = wid & 3;
    const int m0   = blockIdx.y * 128;
    const int n0   = blockIdx.x * 128;

    const int nk = K >> 5;

    float acc[4][4][4];
    #pragma unroll
    for (int i = 0; i < 4; i++)
        #pragma unroll
        for (int j = 0; j < 4; j++)
            #pragma unroll
            for (int q = 0; q < 4; q++) acc[i][j][q] = 0.0f;

    auto load_stage = [&](int kt, int buf) {
        int k0 = kt << 5;
        uint32_t sb0 = sbase + buf * G_STAGE;
        #pragma unroll
        for (int l = 0; l < 8; l++) {
            int c    = tid + l * 256;
            int tile = c >> 9;
            int rem  = c & 511;
            int row  = rem >> 2, ch = rem & 3;
            int chs  = ch ^ ((row >> 1) & 3);
            const __nv_bfloat16* src;
            int rbase;
            if (tile == 0)      { src = Ahi; rbase = m0; }
            else if (tile == 1) { src = Alo; rbase = m0; }
            else if (tile == 2) { src = Whi; rbase = n0; }
            else                { src = Wlo; rbase = n0; }
            CP_ASYNC16(sb0 + tile * G_TILE + row * 64 + chs * 16,
                       src + (size_t)(rbase + row) * K + k0 + ch * 8);
        }
        CP_COMMIT();
    };

    load_stage(0, 0);
    if (nk > 1) load_stage(1, 1);

    const int      xf       = (lane >> 1) & 3;
    const uint32_t a_rowoff = (uint32_t)(wm * 64 + (lane & 15)) * 64;
    const uint32_t b_rowoff = (uint32_t)(wn * 32 + (lane & 7)
                                         + ((lane >> 4) & 1) * 8) * 64;
    const int ca_base = lane >> 4;
    const int cb_base = (lane >> 3) & 1;

    for (int kt = 0; kt < nk; kt++) {
        if (kt + 1 < nk) cp_wait<1>(); else cp_wait<0>();
        __syncthreads();
        if (kt + 2 < nk) load_stage(kt + 2, (kt + 2) % G_NSTAGE);

        const uint32_t stg = sbase + (kt % G_NSTAGE) * G_STAGE;
        const uint32_t aAh = stg + a_rowoff;
        const uint32_t aAl = aAh + G_TILE;
        const uint32_t aWh = stg + 2 * G_TILE + b_rowoff;
        const uint32_t aWl = aWh + G_TILE;

        #pragma unroll
        for (int ks = 0; ks < 2; ks++) {
            const uint32_t ao = (uint32_t)(((ks * 2 + ca_base) ^ xf) * 16);
            const uint32_t bo = (uint32_t)(((ks * 2 + cb_base) ^ xf) * 16);
            uint32_t ah[4][4];
            #pragma unroll
            for (int mt = 0; mt < 4; mt++)
                LDSM4(ah[mt], aAh + mt * 1024 + ao);
            uint32_t bh[2][4];
            #pragma unroll
            for (int nt2 = 0; nt2 < 2; nt2++)
                LDSM4(bh[nt2], aWh + nt2 * 1024 + bo);
            uint32_t bl[2][4];
            #pragma unroll
            for (int nt2 = 0; nt2 < 2; nt2++)
                LDSM4(bl[nt2], aWl + nt2 * 1024 + bo);
            // term 1: Ahi * Whi
            #pragma unroll
            for (int mt = 0; mt < 4; mt++)
                #pragma unroll
                for (int nt = 0; nt < 4; nt++)
                    MMA16816(acc[mt][nt], ah[mt],
                             bh[nt >> 1][(nt & 1) * 2],
                             bh[nt >> 1][(nt & 1) * 2 + 1]);
            // term 2: Ahi * Wlo
            #pragma unroll
            for (int mt = 0; mt < 4; mt++)
                #pragma unroll
                for (int nt = 0; nt < 4; nt++)
                    MMA16816(acc[mt][nt], ah[mt],
                             bl[nt >> 1][(nt & 1) * 2],
                             bl[nt >> 1][(nt & 1) * 2 + 1]);
            // term 3: Alo * Whi
            {
                uint32_t al[4][4];
                #pragma unroll
                for (int mt = 0; mt < 4; mt++)
                    LDSM4(al[mt], aAl + mt * 1024 + ao);
                #pragma unroll
                for (int mt = 0; mt < 4; mt++)
                    #pragma unroll
                    for (int nt = 0; nt < 4; nt++)
                        MMA16816(acc[mt][nt], al[mt],
                                 bh[nt >> 1][(nt & 1) * 2],
                                 bh[nt >> 1][(nt & 1) * 2 + 1]);
            }
        }
    }

    #pragma unroll
    for (int mt = 0; mt < 4; mt++) {
        int row0 = m0 + wm * 64 + mt * 16 + (lane >> 2);
        #pragma unroll
        for (int nt = 0; nt < 4; nt++) {
            int col = n0 + wn * 32 + nt * 8 + 2 * (lane & 3);
            float2 v0 = make_float2(acc[mt][nt][0], acc[mt][nt][1]);
            float2 v1 = make_float2(acc[mt][nt][2], acc[mt][nt][3]);
            *reinterpret_cast<float2*>(&C[(size_t)row0 * N + col])       = v0;
            *reinterpret_cast<float2*>(&C[(size_t)(row0 + 8) * N + col]) = v1;
        }
    }
}

// ---------------------------------------------------------------------------
// RoPE + split from fused g_qkv.  One thread per (token, dp); sincos computed
// once and reused for all 32 Q heads + 8 K heads.  (R16 — measured win.)
// ---------------------------------------------------------------------------
__device__ __forceinline__ void split_store(__nv_bfloat16* hi, __nv_bfloat16* lo,
                                            size_t o, float x) {
    __nv_bfloat16 h = __float2bfloat16_rn(x);
    hi[o] = h;
    lo[o] = __float2bfloat16_rn(x - __bfloat162float(h));
}

__global__ void rope_split_kernel(const int* __restrict__ pos)
{
    const float QS = 0.08838834764831845f * 1.4426950408889634f; // 1/sqrt(128)*log2(e)
    int idx = blockIdx.x * blockDim.x + threadIdx.x;
    const int nqk = M_TOK * 64;              // one thread per (token, dp)
    const int nv  = M_TOK * KH_ * 64;

    if (idx < nqk) {
        int dp = idx & 63;
        int t  = idx >> 6;
        float p   = (float)pos[t];
        float ang = p * exp2f((float)dp * (-19.931568569324174f / 64.0f));
        float sn, cs;
        sincosf(ang, &sn, &cs);
        const float* tb = g_qkv + (size_t)t * NQKV;

        // Q heads: rope + scale + split
        #pragma unroll 4
        for (int hh = 0; hh < H_; hh++) {
            const float* base = tb + hh * D_;
            float x1 = base[dp], x2 = base[dp + 64];
            float y1 = (x1 * cs - x2 * sn) * QS;
            float y2 = (x2 * cs + x1 * sn) * QS;
            size_t o = ((size_t)t * H_ + hh) * D_;
            split_store(g_qh, g_ql, o + dp,      y1);
            split_store(g_qh, g_ql, o + dp + 64, y2);
        }
        // K heads: rope + split
        #pragma unroll
        for (int hh = 0; hh < KH_; hh++) {
            const float* base = tb + H_*D_ + hh * D_;
            float x1 = base[dp], x2 = base[dp + 64];
            float y1 = x1 * cs - x2 * sn;
            float y2 = x2 * cs + x1 * sn;
            size_t o = ((size_t)t * KH_ + hh) * D_;
            split_store(g_kh, g_kl, o + dp,      y1);
            split_store(g_kh, g_kl, o + dp + 64, y2);
        }
        return;
    }
    idx -= nqk;
    if (idx >= nv) return;
    {
        int dp = idx & 63; int r = idx >> 6;
        int hh = r & 7;    int t = r >> 3;
        const float* base = g_qkv + (size_t)t * NQKV + H_*D_ + KH_*D_ + hh * D_;
        size_t o = ((size_t)t * KH_ + hh) * D_;
        split_store(g_vh, g_vl, o + dp,      base[dp]);
        split_store(g_vh, g_vl, o + dp + 64, base[dp + 64]);
    }
}

// ---------------------------------------------------------------------------
// HMMA flash attention, split-bf16 3-term QK and PV.  (R14 verbatim — best.)
// 3-stage KV ring (wait_group<1>), one barrier per iteration.
// Epilogue writes hi/lo bf16 splits directly into g_Ahi/g_Alo (O-proj input).
// ---------------------------------------------------------------------------
#define AT_STRIDE 272
#define AT_SUBT   (64 * AT_STRIDE)
#define AT_STAGE  (4 * AT_SUBT)      // 69632
#define AT_NSTAGE 3
#define AT_SMEM   (AT_NSTAGE * AT_STAGE)   // 208896
#define NEGINF    (-1e30f)
#define MFLOOR    (-1e4f)

__global__ __launch_bounds__(256, 1)
void attn_mma_kernel()
{
    extern __shared__ char smraw[];
    const uint32_t sb = smem_u32(smraw);
    const int tid = threadIdx.x, wid = tid >> 5, lane = tid & 31;
    const int q0 = blockIdx.x * 128;
    const int h  = blockIdx.y;
    const int b  = blockIdx.z;
    const int kh = h >> 2;

    // ---- stage Q (hi, lo) into stage-0 region, read to registers ----
    #pragma unroll
    for (int l = 0; l < 16; l++) {
        int c    = tid + l * 256;
        int half = c >> 11;
        int rem  = c & 2047;
        int row  = rem >> 4, ch = rem & 15;
        const __nv_bfloat16* src = half ? g_ql : g_qh;
        uint32_t sa = sb + half * (128 * AT_STRIDE) + row * AT_STRIDE + ch * 16;
        CP_ASYNC16(sa, src + ((size_t)(b * S_ + q0 + row) * H_ + h) * D_ + ch * 8);
    }
    CP_COMMIT();
    cp_wait<0>();
    __syncthreads();

    uint32_t qfh[8][4], qfl[8][4];
    {
        uint32_t qa = sb + (uint32_t)(wid * 16 + (lane & 15)) * AT_STRIDE
                    + ((lane >> 4) & 1) * 16;
        #pragma unroll
        for (int ks = 0; ks < 8; ks++) {
            LDSM4(qfh[ks], qa + ks * 32);
            LDSM4(qfl[ks], qa + 128 * AT_STRIDE + ks * 32);
        }
    }
    __syncthreads();

    float o[16][4];
    #pragma unroll
    for (int i = 0; i < 16; i++)
        #pragma unroll
        for (int j = 0; j < 4; j++) o[i][j] = 0.0f;
    float m0 = MFLOOR, m1 = MFLOOR, l0 = 0.0f, l1 = 0.0f;

    int lotok = q0 - WIN_ + 1; if (lotok < 0) lotok = 0;
    const int jt0 = lotok >> 6;
    const int jt1 = (q0 + 127) >> 6;

    auto load_kv = [&](int jt, int stg) {
        int j0 = jt << 6;
        const __nv_bfloat16* srcs[4] = {g_kh, g_kl, g_vh, g_vl};
        #pragma unroll
        for (int l = 0; l < 16; l++) {
            int c   = tid + l * 256;
            int sub = c >> 10;
            int rem = c & 1023;
            int row = rem >> 4, ch = rem & 15;
            uint32_t sa = sb + stg * AT_STAGE + sub * AT_SUBT
                        + row * AT_STRIDE + ch * 16;
            CP_ASYNC16(sa, srcs[sub] +
                       ((size_t)(b * S_ + j0 + row) * KH_ + kh) * D_ + ch * 8);
        }
        CP_COMMIT();
    };

    load_kv(jt0, 0);
    if (jt0 + 1 <= jt1) load_kv(jt0 + 1, 1);

    const uint32_t kb_off = (uint32_t)((lane & 7) + ((lane >> 4) & 1) * 8) * AT_STRIDE
                          + ((lane >> 3) & 1) * 16;
    const uint32_t vt_off = (uint32_t)((lane & 7) + ((lane >> 3) & 1) * 8) * AT_STRIDE
                          + (lane >> 4) * 16;

    const int rbase0 = q0 + wid * 16 + (lane >> 2);

    for (int jt = jt0; jt <= jt1; jt++) {
        const int j0 = jt << 6;
        if (jt < jt1) cp_wait<1>(); else cp_wait<0>();
        __syncthreads();
        if (jt + 2 <= jt1) load_kv(jt + 2, (jt + 2 - jt0) % AT_NSTAGE);

        const uint32_t stgb = sb + ((jt - jt0) % AT_NSTAGE) * AT_STAGE;

        float s[8][4];
        #pragma unroll
        for (int i = 0; i < 8; i++)
            #pragma unroll
            for (int j = 0; j < 4; j++) s[i][j] = 0.0f;

        #pragma unroll
        for (int ks = 0; ks < 8; ks++) {
            #pragma unroll
            for (int nt2 = 0; nt2 < 4; nt2++) {
                uint32_t a = stgb + kb_off + (uint32_t)nt2 * (16 * AT_STRIDE) + ks * 32;
                uint32_t kf[4];
                LDSM4(kf, a);
                MMA16816(s[2*nt2],   qfh[ks], kf[0], kf[1]);
                MMA16816(s[2*nt2+1], qfh[ks], kf[2], kf[3]);
                MMA16816(s[2*nt2],   qfl[ks], kf[0], kf[1]);
                MMA16816(s[2*nt2+1], qfl[ks], kf[2], kf[3]);
                LDSM4(kf, a + AT_SUBT);
                MMA16816(s[2*nt2],   qfh[ks], kf[0], kf[1]);
                MMA16816(s[2*nt2+1], qfh[ks], kf[2], kf[3]);
            }
        }

        const bool needM = (j0 + 63 > q0) || ((q0 + 127 - j0) >= WIN_);
        if (needM) {
            #pragma unroll
            for (int nt = 0; nt < 8; nt++) {
                int colb = j0 + nt * 8 + 2 * (lane & 3);
                #pragma unroll
                for (int e = 0; e < 4; e++) {
                    int col = colb + (e & 1);
                    int row = rbase0 + (e >> 1) * 8;
                    if (col > row || (row - col) >= WIN_) s[nt][e] = NEGINF;
                }
            }
        }

        float t0 = NEGINF, t1 = NEGINF;
        #pragma unroll
        for (int nt = 0; nt < 8; nt++) {
            t0 = fmaxf(t0, fmaxf(s[nt][0], s[nt][1]));
            t1 = fmaxf(t1, fmaxf(s[nt][2], s[nt][3]));
        }
        t0 = fmaxf(t0, __shfl_xor_sync(0xffffffffu, t0, 1));
        t0 = fmaxf(t0, __shfl_xor_sync(0xffffffffu, t0, 2));
        t1 = fmaxf(t1, __shfl_xor_sync(0xffffffffu, t1, 1));
        t1 = fmaxf(t1, __shfl_xor_sync(0xffffffffu, t1, 2));
        float n0 = fmaxf(fmaxf(m0, t0), MFLOOR);
        float n1 = fmaxf(fmaxf(m1, t1), MFLOOR);
        float sc0 = ex2(m0 - n0);
        float sc1 = ex2(m1 - n1);
        float rs0 = 0.0f, rs1 = 0.0f;
        #pragma unroll
        for (int nt = 0; nt < 8; nt++) {
            s[nt][0] = ex2(s[nt][0] - n0); rs0 += s[nt][0];
            s[nt][1] = ex2(s[nt][1] - n0); rs0 += s[nt][1];
            s[nt][2] = ex2(s[nt][2] - n1); rs1 += s[nt][2];
            s[nt][3] = ex2(s[nt][3] - n1); rs1 += s[nt][3];
        }
        rs0 += __shfl_xor_sync(0xffffffffu, rs0, 1);
        rs0 += __shfl_xor_sync(0xffffffffu, rs0, 2);
        rs1 += __shfl_xor_sync(0xffffffffu, rs1, 1);
        rs1 += __shfl_xor_sync(0xffffffffu, rs1, 2);
        l0 = l0 * sc0 + rs0;
        l1 = l1 * sc1 + rs1;
        m0 = n0; m1 = n1;
        #pragma unroll
        for (int nt = 0; nt < 16; nt++) {
            o[nt][0] *= sc0; o[nt][1] *= sc0;
            o[nt][2] *= sc1; o[nt][3] *= sc1;
        }

        uint32_t aph[4][4], apl[4][4];
        #pragma unroll
        for (int ks = 0; ks < 4; ks++) {
            #pragma unroll
            for (int half = 0; half < 2; half++) {
                float x0 = s[2*ks + half][0], x1 = s[2*ks + half][1];
                float x2 = s[2*ks + half][2], x3 = s[2*ks + half][3];
                uint32_t h01 = pack_bf2(x0, x1);
                uint32_t h23 = pack_bf2(x2, x3);
                __nv_bfloat162 hb01, hb23;
                memcpy(&hb01, &h01, 4);
                memcpy(&hb23, &h23, 4);
                aph[ks][half * 2 + 0] = h01;
                aph[ks][half * 2 + 1] = h23;
                apl[ks][half * 2 + 0] =
                    pack_bf2(x0 - __bfloat162float(hb01.x),
                             x1 - __bfloat162float(hb01.y));
                apl[ks][half * 2 + 1] =
                    pack_bf2(x2 - __bfloat162float(hb23.x),
                             x3 - __bfloat162float(hb23.y));
            }
        }

        const uint32_t vb = stgb + 2 * AT_SUBT + vt_off;
        #pragma unroll
        for (int ks = 0; ks < 4; ks++) {
            #pragma unroll
            for (int dt2 = 0; dt2 < 8; dt2++) {
                uint32_t a = vb + (uint32_t)ks * (16 * AT_STRIDE) + dt2 * 32;
                uint32_t vf[4];
                LDSM4T(vf, a);
                MMA16816(o[2*dt2],   aph[ks], vf[0], vf[1]);
                MMA16816(o[2*dt2+1], aph[ks], vf[2], vf[3]);
                MMA16816(o[2*dt2],   apl[ks], vf[0], vf[1]);
                MMA16816(o[2*dt2+1], apl[ks], vf[2], vf[3]);
                LDSM4T(vf, a + AT_SUBT);
                MMA16816(o[2*dt2],   aph[ks], vf[0], vf[1]);
                MMA16816(o[2*dt2+1], aph[ks], vf[2], vf[3]);
            }
        }
        // no trailing barrier: next iteration's top barrier protects stage reuse
    }

    // ---- epilogue: normalize and write bf16 hi/lo directly (O-proj input) ----
    float i0v = 1.0f / l0, i1v = 1.0f / l1;
    size_t r0 = (size_t)(b * S_ + rbase0);
    size_t r1 = r0 + 8;
    __nv_bfloat16* hi0 = g_Ahi + r0 * HID_ + h * D_;
    __nv_bfloat16* lo0 = g_Alo + r0 * HID_ + h * D_;
    __nv_bfloat16* hi1 = g_Ahi + r1 * HID_ + h * D_;
    __nv_bfloat16* lo1 = g_Alo + r1 * HID_ + h * D_;
    #pragma unroll
    for (int nt = 0; nt < 16; nt++) {
        int colb = nt * 8 + 2 * (lane & 3);
        float x0 = o[nt][0] * i0v, x1 = o[nt][1] * i0v;
        float x2 = o[nt][2] * i1v, x3 = o[nt][3] * i1v;
        __nv_bfloat162 h01 = __floats2bfloat162_rn(x0, x1);
        __nv_bfloat162 h23 = __floats2bfloat162_rn(x2, x3);
        __nv_bfloat162 l01 = __floats2bfloat162_rn(x0 - __bfloat162float(h01.x),
                                                   x1 - __bfloat162float(h01.y));
        __nv_bfloat162 l23 = __floats2bfloat162_rn(x2 - __bfloat162float(h23.x),
                                                   x3 - __bfloat162float(h23.y));
        *reinterpret_cast<__nv_bfloat162*>(hi0 + colb) = h01;
        *reinterpret_cast<__nv_bfloat162*>(lo0 + colb) = l01;
        *reinterpret_cast<__nv_bfloat162*>(hi1 + colb) = h23;
        *reinterpret_cast<__nv_bfloat162*>(lo1 + colb) = l23;
    }
}

// ---------------------------------------------------------------------------
extern "C" void kernel_launch(void* const* d_in, const int* in_sizes, int n_in,
                              void* d_out, int out_size)
{
    const float* hidden = (const float*)d_in[0];
    const int*   pos    = (const int*)  d_in[1];
    const float* wq     = (const float*)d_in[2];
    const float* wk     = (const float*)d_in[3];
    const float* wv     = (const float*)d_in[4];
    const float* wo     = (const float*)d_in[5];
    float* out = (float*)d_out;

    float *gqkv;
    __nv_bfloat16 *ahi, *alo, *wqkvh, *wqkvl, *woh, *wol;
    cudaGetSymbolAddress((void**)&gqkv,  g_qkv);
    cudaGetSymbolAddress((void**)&ahi,   g_Ahi);
    cudaGetSymbolAddress((void**)&alo,   g_Alo);
    cudaGetSymbolAddress((void**)&wqkvh, g_Wqkvhi);
    cudaGetSymbolAddress((void**)&wqkvl, g_Wqkvlo);
    cudaGetSymbolAddress((void**)&woh,   g_Wohi);
    cudaGetSymbolAddress((void**)&wol,   g_Wolo);

    cudaFuncSetAttribute(gemm_split_kernel,
                         cudaFuncAttributeMaxDynamicSharedMemorySize, GEMM_SMEM);
    cudaFuncSetAttribute(attn_mma_kernel,
                         cudaFuncAttributeMaxDynamicSharedMemorySize, AT_SMEM);

    // ---- split inputs (5 launches; split_T now 64x32 tiles, paired stores) ----
    split_kernel<<<(M_TOK * HID_ / 4 + 255) / 256, 256>>>(hidden, ahi, alo,
                                                          M_TOK * HID_ / 4);
    split_T_kernel<<<dim3((H_*D_)/32,  HID_/64), 256>>>(
        wq, wqkvh, wqkvl, HID_, H_*D_);
    split_T_kernel<<<dim3((KH_*D_)/32, HID_/64), 256>>>(
        wk, wqkvh + (size_t)(H_*D_) * HID_, wqkvl + (size_t)(H_*D_) * HID_,
        HID_, KH_*D_);
    split_T_kernel<<<dim3((KH_*D_)/32, HID_/64), 256>>>(
        wv, wqkvh + (size_t)(H_*D_ + KH_*D_) * HID_,
        wqkvl + (size_t)(H_*D_ + KH_*D_) * HID_, HID_, KH_*D_);
    split_T_kernel<<<dim3(HID_/32, (H_*D_)/64), 256>>>(
        wo, woh, wol, H_*D_, HID_);

    // ---- fused QKV projection ----
    gemm_split_kernel<<<dim3(NQKV/128, M_TOK/128), 256, GEMM_SMEM>>>(
        ahi, alo, wqkvh, wqkvl, gqkv, M_TOK, NQKV, HID_);

    // ---- RoPE + attention-operand splits (sincos amortized over heads) ----
    {
        int total = M_TOK * 64 + M_TOK * KH_ * 64;
        rope_split_kernel<<<(total + 255) / 256, 256>>>(pos);
    }

    // ---- attention (HMMA); writes O-proj inputs g_Ahi/g_Alo directly ----
    attn_mma_kernel<<<dim3(S_ / 128, H_, B_), 256, AT_SMEM>>>();

    // ---- output projection ----
    gemm_split_kernel<<<dim3(HID_/128, M_TOK/128), 256, GEMM_SMEM>>>(
        ahi, alo, woh, wol, out, M_TOK, HID_, H_*D_);
}